// round 2
// baseline (speedup 1.0000x reference)
#include <cuda_runtime.h>

#define NNODES 4000
#define BATCH  64
#define CIN    64
#define COUT   64
#define EMBD   10

// Scratch (allocation-free rule: __device__ globals)
__device__ float g_S [(size_t)NNODES * NNODES];        // 64 MB softmax adjacency
__device__ float g_y1[(size_t)BATCH * NNODES * CIN];   // S @ x
__device__ float g_y2[(size_t)BATCH * NNODES * CIN];   // S @ (S @ x)

// ---------------------------------------------------------------------------
// Kernel 1: S = softmax(relu(E E^T), axis=1). One block per row.
// ---------------------------------------------------------------------------
__global__ __launch_bounds__(256) void supports_kernel(const float* __restrict__ emb) {
    __shared__ float logits[NNODES];      // 16000 B
    __shared__ float en[EMBD];
    __shared__ float red[256];
    const int n = blockIdx.x;
    const int t = threadIdx.x;
    if (t < EMBD) en[t] = emb[n * EMBD + t];
    __syncthreads();

    float lmax = 0.0f;  // relu => values >= 0
    for (int m = t; m < NNODES; m += 256) {
        const float* em = emb + m * EMBD;
        float d = 0.f;
        #pragma unroll
        for (int i = 0; i < EMBD; i++) d += en[i] * em[i];
        d = fmaxf(d, 0.f);
        logits[m] = d;
        lmax = fmaxf(lmax, d);
    }
    red[t] = lmax; __syncthreads();
    for (int s = 128; s > 0; s >>= 1) {
        if (t < s) red[t] = fmaxf(red[t], red[t + s]);
        __syncthreads();
    }
    const float mx = red[0];
    __syncthreads();

    float lsum = 0.f;
    for (int m = t; m < NNODES; m += 256) {
        float e = __expf(logits[m] - mx);
        logits[m] = e;
        lsum += e;
    }
    red[t] = lsum; __syncthreads();
    for (int s = 128; s > 0; s >>= 1) {
        if (t < s) red[t] += red[t + s];
        __syncthreads();
    }
    const float inv = 1.0f / red[0];
    float* Srow = g_S + (size_t)n * NNODES;
    for (int m = t; m < NNODES; m += 256) Srow[m] = logits[m] * inv;
}

// ---------------------------------------------------------------------------
// Kernel 2: Y[b] = S @ X[b] for all b.  PHASE 0: X = x (harness), Y = g_y1.
//                                       PHASE 1: X = g_y1,       Y = g_y2.
// Tile: 128(M) x 64(N) x 16(K), 256 threads, 8x4 per-thread microtile,
// register-staged global prefetch overlapping the FMA loop.
// ---------------------------------------------------------------------------
template <int PHASE>
__global__ __launch_bounds__(256) void gemm_SX(const float* __restrict__ Xext) {
    const float* __restrict__ X = (PHASE == 0) ? Xext : (const float*)g_y1;
    float* __restrict__ Y       = (PHASE == 0) ? g_y1 : g_y2;

    __shared__ __align__(16) float As[16][128];   // transposed: As[k][row]
    __shared__ __align__(16) float Bs[16][64];

    const int t  = threadIdx.x;
    const int r0 = blockIdx.x * 128;
    const float* __restrict__ Xb = X + (size_t)blockIdx.y * (NNODES * CIN);
    float* __restrict__ Yb       = Y + (size_t)blockIdx.y * (NNODES * CIN);

    const int tr = t >> 4, tc = t & 15;        // compute mapping
    const int rowA = t >> 2, kqA = t & 3;      // A-load mapping (rows rowA, rowA+64)
    const int krX = t >> 4, c4X = t & 15;      // X-load mapping

    float acc[8][4];
    #pragma unroll
    for (int i = 0; i < 8; i++)
        #pragma unroll
        for (int j = 0; j < 4; j++) acc[i][j] = 0.f;

    float4 aReg0, aReg1, xReg;
    {   // prologue: tile kt = 0
        const int g0 = r0 + rowA, g1 = g0 + 64;
        aReg0 = (g0 < NNODES) ? *(const float4*)&g_S[(size_t)g0 * NNODES + kqA * 4]
                              : make_float4(0.f, 0.f, 0.f, 0.f);
        aReg1 = (g1 < NNODES) ? *(const float4*)&g_S[(size_t)g1 * NNODES + kqA * 4]
                              : make_float4(0.f, 0.f, 0.f, 0.f);
        xReg  = *(const float4*)&Xb[(size_t)krX * CIN + c4X * 4];
    }

    for (int kt = 0; kt < NNODES; kt += 16) {
        // stage registers -> shared
        As[kqA * 4 + 0][rowA]      = aReg0.x;
        As[kqA * 4 + 1][rowA]      = aReg0.y;
        As[kqA * 4 + 2][rowA]      = aReg0.z;
        As[kqA * 4 + 3][rowA]      = aReg0.w;
        As[kqA * 4 + 0][rowA + 64] = aReg1.x;
        As[kqA * 4 + 1][rowA + 64] = aReg1.y;
        As[kqA * 4 + 2][rowA + 64] = aReg1.z;
        As[kqA * 4 + 3][rowA + 64] = aReg1.w;
        *(float4*)&Bs[krX][c4X * 4] = xReg;
        __syncthreads();

        const int ktn = kt + 16;
        if (ktn < NNODES) {   // prefetch next tile (hidden under FMA loop)
            const int g0 = r0 + rowA, g1 = g0 + 64;
            aReg0 = (g0 < NNODES) ? *(const float4*)&g_S[(size_t)g0 * NNODES + ktn + kqA * 4]
                                  : make_float4(0.f, 0.f, 0.f, 0.f);
            aReg1 = (g1 < NNODES) ? *(const float4*)&g_S[(size_t)g1 * NNODES + ktn + kqA * 4]
                                  : make_float4(0.f, 0.f, 0.f, 0.f);
            xReg  = *(const float4*)&Xb[(size_t)(ktn + krX) * CIN + c4X * 4];
        }

        #pragma unroll
        for (int kk = 0; kk < 16; kk++) {
            const float4 a0 = *(const float4*)&As[kk][tr * 8];
            const float4 a1 = *(const float4*)&As[kk][tr * 8 + 4];
            const float4 bv = *(const float4*)&Bs[kk][tc * 4];
            const float ar[8] = {a0.x, a0.y, a0.z, a0.w, a1.x, a1.y, a1.z, a1.w};
            #pragma unroll
            for (int i = 0; i < 8; i++) {
                acc[i][0] += ar[i] * bv.x;
                acc[i][1] += ar[i] * bv.y;
                acc[i][2] += ar[i] * bv.z;
                acc[i][3] += ar[i] * bv.w;
            }
        }
        __syncthreads();
    }

    #pragma unroll
    for (int i = 0; i < 8; i++) {
        const int grow = r0 + tr * 8 + i;
        if (grow < NNODES) {
            *(float4*)&Yb[(size_t)grow * CIN + tc * 4] =
                make_float4(acc[i][0], acc[i][1], acc[i][2], acc[i][3]);
        }
    }
}

// ---------------------------------------------------------------------------
// Kernel 3: out[b,n,o] = sum_{k,i} xg_k[b,n,i] * W_k[n,i,o] + bias[n,o]
//   xg_0 = x, xg_1 = y1, xg_2 = 2*y2 - x
//   W_k[n,i,o] = sum_d emb[n,d] * Wpool[d,k,i,o];  bias[n,o] = emb[n,:] @ bp[:,o]
// One block per node n; 256 threads; 4(b) x 4(o) per-thread microtile.
// ---------------------------------------------------------------------------
__global__ __launch_bounds__(256) void final_kernel(const float* __restrict__ x,
                                                    const float* __restrict__ emb,
                                                    const float* __restrict__ wp,
                                                    const float* __restrict__ bp,
                                                    float* __restrict__ out) {
    __shared__ __align__(16) float Ws[CIN][COUT];    // 16 KB
    __shared__ __align__(16) float Xs[BATCH][68];    // padded stride: no bank conflicts
    __shared__ float en[EMBD];
    __shared__ float bias_s[COUT];

    const int n = blockIdx.x;
    const int t = threadIdx.x;
    if (t < EMBD) en[t] = emb[n * EMBD + t];
    __syncthreads();
    if (t < COUT) {
        float s = 0.f;
        #pragma unroll
        for (int d = 0; d < EMBD; d++) s += en[d] * bp[d * COUT + t];
        bias_s[t] = s;
    }
    __syncthreads();

    const int ob = (t & 15) * 4;   // 4 consecutive outputs
    const int bb = (t >> 4) * 4;   // 4 batches
    float acc[4][4];
    #pragma unroll
    for (int bi = 0; bi < 4; bi++)
        #pragma unroll
        for (int oi = 0; oi < 4; oi++) acc[bi][oi] = bias_s[ob + oi];

    for (int k = 0; k < 3; k++) {
        __syncthreads();   // previous phase's shared reads done

        // generate per-node weights W_k[i][o] into shared
        #pragma unroll
        for (int j = 0; j < 4; j++) {
            const int q  = t + 256 * j;     // 1024 float4 slots
            const int i  = q >> 4;
            const int o4 = (q & 15) * 4;
            float4 w = make_float4(0.f, 0.f, 0.f, 0.f);
            #pragma unroll
            for (int d = 0; d < EMBD; d++) {
                const float4 wv = *(const float4*)&wp[(((d * 3 + k) * CIN + i) * COUT) + o4];
                const float ed = en[d];
                w.x += ed * wv.x; w.y += ed * wv.y;
                w.z += ed * wv.z; w.w += ed * wv.w;
            }
            *(float4*)&Ws[i][o4] = w;
        }

        // load xg_k rows for all batches into shared
        #pragma unroll
        for (int j = 0; j < 4; j++) {
            const int q  = t + 256 * j;
            const int b  = q >> 4;
            const int c4 = (q & 15) * 4;
            const size_t off = ((size_t)b * NNODES + n) * CIN + c4;
            float4 v;
            if (k == 0)      v = *(const float4*)&x[off];
            else if (k == 1) v = *(const float4*)&g_y1[off];
            else {
                const float4 v2 = *(const float4*)&g_y2[off];
                const float4 vx = *(const float4*)&x[off];
                v = make_float4(2.f * v2.x - vx.x, 2.f * v2.y - vx.y,
                                2.f * v2.z - vx.z, 2.f * v2.w - vx.w);
            }
            *(float4*)&Xs[b][c4] = v;
        }
        __syncthreads();

        #pragma unroll 8
        for (int i = 0; i < CIN; i++) {
            const float4 w = *(const float4*)&Ws[i][ob];
            float xr[4];
            #pragma unroll
            for (int bi = 0; bi < 4; bi++) xr[bi] = Xs[bb + bi][i];
            #pragma unroll
            for (int bi = 0; bi < 4; bi++) {
                acc[bi][0] += xr[bi] * w.x;
                acc[bi][1] += xr[bi] * w.y;
                acc[bi][2] += xr[bi] * w.z;
                acc[bi][3] += xr[bi] * w.w;
            }
        }
    }

    #pragma unroll
    for (int bi = 0; bi < 4; bi++) {
        const size_t off = ((size_t)(bb + bi) * NNODES + n) * COUT + ob;
        *(float4*)&out[off] = make_float4(acc[bi][0], acc[bi][1], acc[bi][2], acc[bi][3]);
    }
}

// ---------------------------------------------------------------------------
extern "C" void kernel_launch(void* const* d_in, const int* in_sizes, int n_in,
                              void* d_out, int out_size) {
    const float* x   = (const float*)d_in[0];   // [B, N, CIN]
    const float* emb = (const float*)d_in[1];   // [N, D]
    const float* wp  = (const float*)d_in[2];   // [D, K, CIN, COUT]
    const float* bp  = (const float*)d_in[3];   // [D, COUT]
    float* out = (float*)d_out;                 // [B, N, COUT]

    supports_kernel<<<NNODES, 256>>>(emb);

    dim3 g((NNODES + 127) / 128, BATCH);        // 32 x 64
    gemm_SX<0><<<g, 256>>>(x);                  // y1 = S @ x
    gemm_SX<1><<<g, 256>>>(x);                  // y2 = S @ y1

    final_kernel<<<NNODES, 256>>>(x, emb, wp, bp, out);
}

// round 5
// speedup vs baseline: 3.1540x; 3.1540x over previous
#include <cuda_runtime.h>
#include <cstdint>

#define NNODES 4000
#define NPAD   4096
#define BATCH  64
#define CIN    64
#define COUT   64
#define EMBD   10
#define JDIM   4096            // BATCH * CIN
#define KTILES 125             // 4000 / 32
#define BM     128
#define BN     128
#define BK     32
#define PADK   36              // smem row stride in floats (36 % 32 == 4 -> conflict-free)
#define STAGE_FLOATS (BM * PADK)          // 4608 floats = 18432 B per operand per stage
#define GSMEM  (4 * STAGE_FLOATS * 4)     // 2 stages * (A+B) = 73728 B

// Scratch (allocation-free rule: __device__ globals; zero-initialized at load)
__device__ float g_S  [(size_t)NPAD * NNODES];   // rows 4000..4095 stay zero forever
__device__ float g_Xt [(size_t)JDIM * NNODES];   // x transposed (tf32-rounded): [(b*64+c), m]
__device__ float g_y1t[(size_t)JDIM * NNODES];   // y1 transposed (tf32-rounded), B of GEMM2
__device__ float g_y1n[(size_t)BATCH * NNODES * CIN];
__device__ float g_y2n[(size_t)BATCH * NNODES * CIN];

// ---------------------------------------------------------------------------
// helpers
// ---------------------------------------------------------------------------
__device__ __forceinline__ uint32_t smem_u32(const void* p) {
    uint32_t a;
    asm("{ .reg .u64 t; cvta.to.shared.u64 t, %1; cvt.u32.u64 %0, t; }" : "=r"(a) : "l"(p));
    return a;
}
__device__ __forceinline__ void cp16(uint32_t dst, const void* src) {
    asm volatile("cp.async.cg.shared.global [%0], [%1], 16;" :: "r"(dst), "l"(src) : "memory");
}
#define CP_COMMIT() asm volatile("cp.async.commit_group;" ::: "memory")
#define CP_WAIT1()  asm volatile("cp.async.wait_group 1;" ::: "memory")

__device__ __forceinline__ float tf32r(float x) {
    uint32_t o;
    asm("cvt.rna.tf32.f32 %0, %1;" : "=r"(o) : "f"(x));
    return __uint_as_float(o);
}
__device__ __forceinline__ void mma_tf32(float* c, const float* a, const float* b) {
    asm volatile(
        "mma.sync.aligned.m16n8k8.row.col.f32.tf32.tf32.f32 "
        "{%0,%1,%2,%3}, {%4,%5,%6,%7}, {%8,%9}, {%0,%1,%2,%3};"
        : "+f"(c[0]), "+f"(c[1]), "+f"(c[2]), "+f"(c[3])
        : "r"(__float_as_uint(a[0])), "r"(__float_as_uint(a[1])),
          "r"(__float_as_uint(a[2])), "r"(__float_as_uint(a[3])),
          "r"(__float_as_uint(b[0])), "r"(__float_as_uint(b[1])));
}

// ---------------------------------------------------------------------------
// Kernel 1: S = softmax(relu(E E^T), axis=1), rounded to tf32. One block/row.
// ---------------------------------------------------------------------------
__global__ __launch_bounds__(256) void supports_kernel(const float* __restrict__ emb) {
    __shared__ float logits[NNODES];
    __shared__ float en[EMBD];
    __shared__ float red[256];
    const int n = blockIdx.x;
    const int t = threadIdx.x;
    if (t < EMBD) en[t] = emb[n * EMBD + t];
    __syncthreads();

    float lmax = 0.0f;
    for (int m = t; m < NNODES; m += 256) {
        const float* em = emb + m * EMBD;
        float d = 0.f;
        #pragma unroll
        for (int i = 0; i < EMBD; i++) d += en[i] * em[i];
        d = fmaxf(d, 0.f);
        logits[m] = d;
        lmax = fmaxf(lmax, d);
    }
    red[t] = lmax; __syncthreads();
    for (int s = 128; s > 0; s >>= 1) {
        if (t < s) red[t] = fmaxf(red[t], red[t + s]);
        __syncthreads();
    }
    const float mx = red[0];
    __syncthreads();

    float lsum = 0.f;
    for (int m = t; m < NNODES; m += 256) {
        float e = __expf(logits[m] - mx);
        logits[m] = e;
        lsum += e;
    }
    red[t] = lsum; __syncthreads();
    for (int s = 128; s > 0; s >>= 1) {
        if (t < s) red[t] += red[t + s];
        __syncthreads();
    }
    const float inv = 1.0f / red[0];
    float* Srow = g_S + (size_t)n * NNODES;
    for (int m = t; m < NNODES; m += 256) Srow[m] = tf32r(logits[m] * inv);
}

// ---------------------------------------------------------------------------
// Kernel 2: transpose x[b,m,c] -> Xt[(b*64+c), m], rounded to tf32
// ---------------------------------------------------------------------------
__global__ __launch_bounds__(256) void transpose_kernel(const float* __restrict__ x) {
    __shared__ float Ts[128][68];
    const int t  = threadIdx.x;
    const int m0 = blockIdx.x * 128;
    const int b  = blockIdx.y;

    #pragma unroll
    for (int i = 0; i < 8; i++) {
        const int idx = t + 256 * i;
        const int row = idx >> 4, c4 = idx & 15;
        float4 v = make_float4(0.f, 0.f, 0.f, 0.f);
        if (m0 + row < NNODES)
            v = *(const float4*)&x[((size_t)b * NNODES + m0 + row) * CIN + c4 * 4];
        *(float4*)&Ts[row][c4 * 4] = v;
    }
    __syncthreads();

    #pragma unroll
    for (int i = 0; i < 8; i++) {
        const int o  = t + 256 * i;
        const int c  = o >> 5, mk = o & 31;
        const int m  = m0 + mk * 4;
        if (m + 3 < NNODES) {
            float4 v = make_float4(tf32r(Ts[mk*4+0][c]), tf32r(Ts[mk*4+1][c]),
                                   tf32r(Ts[mk*4+2][c]), tf32r(Ts[mk*4+3][c]));
            *(float4*)&g_Xt[(size_t)(b * 64 + c) * NNODES + m] = v;
        }
    }
}

// ---------------------------------------------------------------------------
// Kernel 3: tf32 mma.sync GEMM  C[128,128] = S_tile[128,4000] @ B_tile^T
//   PHASE 0: B = Xt,  outputs y1n (+ y1t rounded)
//   PHASE 1: B = y1t, outputs y2n
// 8 warps as 2(M) x 4(N); warp tile 64x32; 2-stage cp.async double buffer.
// ---------------------------------------------------------------------------
template <int PHASE>
__global__ __launch_bounds__(256, 2) void gemm_mma() {
    extern __shared__ float sm[];
    float* AsF = sm;                         // [2][BM][PADK]
    float* BsF = sm + 2 * STAGE_FLOATS;      // [2][BN][PADK]
    const uint32_t sA = smem_u32(AsF);
    const uint32_t sB = smem_u32(BsF);

    const float* __restrict__ Bmat = (PHASE == 0) ? g_Xt : g_y1t;
    const int m0 = blockIdx.x * BM;
    const int j0 = blockIdx.y * BN;

    const int t    = threadIdx.x;
    const int lane = t & 31, warp = t >> 5;
    const int wm = warp >> 2, wn = warp & 3;
    const int g = lane >> 2, tig = lane & 3;

    const int lr = t >> 3, lq = t & 7;       // load mapping: 32 rows x 8 chunks per 256-pass

    float acc[4][4][4];
    #pragma unroll
    for (int mi = 0; mi < 4; mi++)
        #pragma unroll
        for (int ni = 0; ni < 4; ni++)
            #pragma unroll
            for (int q = 0; q < 4; q++) acc[mi][ni][q] = 0.f;

    // ---- tile loader: A rows from g_S[m0..], B rows from Bmat[j0..]
    auto load_tile = [&](int kt, int s) {
        const size_t kc = (size_t)kt * BK;
        const uint32_t aBase = sA + s * (STAGE_FLOATS * 4);
        const uint32_t bBase = sB + s * (STAGE_FLOATS * 4);
        #pragma unroll
        for (int i = 0; i < 4; i++) {
            const int r = lr + 32 * i;       // 0..127
            cp16(aBase + r * (PADK * 4) + lq * 16,
                 g_S + (size_t)(m0 + r) * NNODES + kc + lq * 4);
            cp16(bBase + r * (PADK * 4) + lq * 16,
                 Bmat + (size_t)(j0 + r) * NNODES + kc + lq * 4);
        }
    };

    load_tile(0, 0);
    CP_COMMIT();

    for (int kt = 0; kt < KTILES; ++kt) {
        if (kt + 1 < KTILES) load_tile(kt + 1, (kt + 1) & 1);
        CP_COMMIT();                          // possibly-empty group keeps the count uniform
        CP_WAIT1();                           // stage kt resident
        __syncthreads();

        const float* As = AsF + (kt & 1) * STAGE_FLOATS;
        const float* Bs = BsF + (kt & 1) * STAGE_FLOATS;

        #pragma unroll
        for (int k8 = 0; k8 < 4; ++k8) {
            float a[4][4], b[4][2];
            #pragma unroll
            for (int mi = 0; mi < 4; mi++) {
                const int row = wm * 64 + mi * 16 + g;
                const int col = k8 * 8 + tig;
                a[mi][0] = As[row * PADK + col];
                a[mi][1] = As[(row + 8) * PADK + col];
                a[mi][2] = As[row * PADK + col + 4];
                a[mi][3] = As[(row + 8) * PADK + col + 4];
            }
            #pragma unroll
            for (int ni = 0; ni < 4; ni++) {
                const int nrow = wn * 32 + ni * 8 + g;
                const int col = k8 * 8 + tig;
                b[ni][0] = Bs[nrow * PADK + col];
                b[ni][1] = Bs[nrow * PADK + col + 4];
            }
            #pragma unroll
            for (int mi = 0; mi < 4; mi++)
                #pragma unroll
                for (int ni = 0; ni < 4; ni++)
                    mma_tf32(acc[mi][ni], a[mi], b[ni]);
        }
        __syncthreads();
    }

    // ---- epilogue: write y*n normal layout (+ y1t transposed for GEMM2)
    float* __restrict__ outn = (PHASE == 0) ? g_y1n : g_y2n;
    #pragma unroll
    for (int mi = 0; mi < 4; mi++) {
        const int m = m0 + wm * 64 + mi * 16 + g;
        #pragma unroll
        for (int ni = 0; ni < 4; ni++) {
            const float* c = acc[mi][ni];
            const int j = j0 + wn * 32 + ni * 8 + tig * 2;
            const int b = j >> 6, cc = j & 63;
            if (m < NNODES) {
                *(float2*)&outn[((size_t)b * NNODES + m) * CIN + cc] = make_float2(c[0], c[1]);
                if (PHASE == 0) {
                    g_y1t[(size_t)j * NNODES + m]       = tf32r(c[0]);
                    g_y1t[(size_t)(j + 1) * NNODES + m] = tf32r(c[1]);
                }
            }
            const int m2 = m + 8;
            if (m2 < NNODES) {
                *(float2*)&outn[((size_t)b * NNODES + m2) * CIN + cc] = make_float2(c[2], c[3]);
                if (PHASE == 0) {
                    g_y1t[(size_t)j * NNODES + m2]       = tf32r(c[2]);
                    g_y1t[(size_t)(j + 1) * NNODES + m2] = tf32r(c[3]);
                }
            }
        }
    }
}

// ---------------------------------------------------------------------------
// Kernel 4: out[b,n,o] = sum_{k,i} xg_k[b,n,i] * W_k[n,i,o] + bias[n,o]
//   xg_0 = x, xg_1 = y1, xg_2 = 2*y2 - x
// ---------------------------------------------------------------------------
__global__ __launch_bounds__(256) void final_kernel(const float* __restrict__ x,
                                                    const float* __restrict__ emb,
                                                    const float* __restrict__ wp,
                                                    const float* __restrict__ bp,
                                                    float* __restrict__ out) {
    __shared__ __align__(16) float Ws[CIN][COUT];
    __shared__ __align__(16) float Xs[BATCH][68];
    __shared__ float en[EMBD];
    __shared__ float bias_s[COUT];

    const int n = blockIdx.x;
    const int t = threadIdx.x;
    if (t < EMBD) en[t] = emb[n * EMBD + t];
    __syncthreads();
    if (t < COUT) {
        float s = 0.f;
        #pragma unroll
        for (int d = 0; d < EMBD; d++) s += en[d] * bp[d * COUT + t];
        bias_s[t] = s;
    }
    __syncthreads();

    const int ob = (t & 15) * 4;
    const int bb = (t >> 4) * 4;
    float acc[4][4];
    #pragma unroll
    for (int bi = 0; bi < 4; bi++)
        #pragma unroll
        for (int oi = 0; oi < 4; oi++) acc[bi][oi] = bias_s[ob + oi];

    for (int k = 0; k < 3; k++) {
        __syncthreads();

        #pragma unroll
        for (int j = 0; j < 4; j++) {
            const int q  = t + 256 * j;
            const int i  = q >> 4;
            const int o4 = (q & 15) * 4;
            float4 w = make_float4(0.f, 0.f, 0.f, 0.f);
            #pragma unroll
            for (int d = 0; d < EMBD; d++) {
                const float4 wv = *(const float4*)&wp[(((d * 3 + k) * CIN + i) * COUT) + o4];
                const float ed = en[d];
                w.x += ed * wv.x; w.y += ed * wv.y;
                w.z += ed * wv.z; w.w += ed * wv.w;
            }
            *(float4*)&Ws[i][o4] = w;
        }

        #pragma unroll
        for (int j = 0; j < 4; j++) {
            const int q  = t + 256 * j;
            const int b  = q >> 4;
            const int c4 = (q & 15) * 4;
            const size_t off = ((size_t)b * NNODES + n) * CIN + c4;
            float4 v;
            if (k == 0)      v = *(const float4*)&x[off];
            else if (k == 1) v = *(const float4*)&g_y1n[off];
            else {
                const float4 v2 = *(const float4*)&g_y2n[off];
                const float4 vx = *(const float4*)&x[off];
                v = make_float4(2.f * v2.x - vx.x, 2.f * v2.y - vx.y,
                                2.f * v2.z - vx.z, 2.f * v2.w - vx.w);
            }
            *(float4*)&Xs[b][c4] = v;
        }
        __syncthreads();

        #pragma unroll 8
        for (int i = 0; i < CIN; i++) {
            const float4 w = *(const float4*)&Ws[i][ob];
            float xr[4];
            #pragma unroll
            for (int bi = 0; bi < 4; bi++) xr[bi] = Xs[bb + bi][i];
            #pragma unroll
            for (int bi = 0; bi < 4; bi++) {
                acc[bi][0] += xr[bi] * w.x;
                acc[bi][1] += xr[bi] * w.y;
                acc[bi][2] += xr[bi] * w.z;
                acc[bi][3] += xr[bi] * w.w;
            }
        }
    }

    #pragma unroll
    for (int bi = 0; bi < 4; bi++) {
        const size_t off = ((size_t)(bb + bi) * NNODES + n) * COUT + ob;
        *(float4*)&out[off] = make_float4(acc[bi][0], acc[bi][1], acc[bi][2], acc[bi][3]);
    }
}

// ---------------------------------------------------------------------------
extern "C" void kernel_launch(void* const* d_in, const int* in_sizes, int n_in,
                              void* d_out, int out_size) {
    const float* x   = (const float*)d_in[0];   // [B, N, CIN]
    const float* emb = (const float*)d_in[1];   // [N, D]
    const float* wp  = (const float*)d_in[2];   // [D, K, CIN, COUT]
    const float* bp  = (const float*)d_in[3];   // [D, COUT]
    float* out = (float*)d_out;                 // [B, N, COUT]

    cudaFuncSetAttribute(gemm_mma<0>, cudaFuncAttributeMaxDynamicSharedMemorySize, GSMEM);
    cudaFuncSetAttribute(gemm_mma<1>, cudaFuncAttributeMaxDynamicSharedMemorySize, GSMEM);

    supports_kernel<<<NNODES, 256>>>(emb);
    transpose_kernel<<<dim3(32, BATCH), 256>>>(x);

    dim3 g(32, 32);                             // Mtiles x Ntiles
    gemm_mma<0><<<g, 256, GSMEM>>>();           // y1 = S @ x   (-> y1n, y1t)
    gemm_mma<1><<<g, 256, GSMEM>>>();           // y2 = S @ y1  (-> y2n)

    final_kernel<<<NNODES, 256>>>(x, emb, wp, bp, out);
}

// round 10
// speedup vs baseline: 3.6690x; 1.1633x over previous
#include <cuda_runtime.h>
#include <cstdint>

#define NNODES 4000
#define NPAD   4096
#define BATCH  64
#define CIN    64
#define COUT   64
#define EMBD   10
#define JDIM   4096            // BATCH * CIN
#define KTILES 125             // 4000 / 32
#define BM     128
#define BN     128
#define BK     32
#define PADK   36              // smem row stride in floats (36 % 32 == 4 -> conflict-free)
#define PADKB  (PADK * 4)      // 144 bytes
#define A_STG  (BM * PADKB)    // 18432 B
#define STAGE_BYTES ((BM + BN) * PADKB)     // 36864 B
#define NSTAGE 3
#define GSMEM  (NSTAGE * STAGE_BYTES)       // 110592 B

// Scratch (allocation-free rule: __device__ globals; zero-initialized at load)
__device__ float g_S  [(size_t)NPAD * NNODES];   // rows 4000..4095 stay zero forever
__device__ float g_Xt [(size_t)JDIM * NNODES];   // x transposed (tf32-rounded): [(b*64+c), m]
__device__ float g_y1t[(size_t)JDIM * NNODES];   // y1 transposed (tf32-rounded), B of GEMM2
__device__ float g_y1n[(size_t)BATCH * NNODES * CIN];
__device__ float g_y2n[(size_t)BATCH * NNODES * CIN];

// ---------------------------------------------------------------------------
// helpers
// ---------------------------------------------------------------------------
__device__ __forceinline__ uint32_t smem_u32(const void* p) {
    uint32_t a;
    asm("{ .reg .u64 t; cvta.to.shared.u64 t, %1; cvt.u32.u64 %0, t; }" : "=r"(a) : "l"(p));
    return a;
}
__device__ __forceinline__ void cp16(uint32_t dst, const void* src) {
    asm volatile("cp.async.cg.shared.global [%0], [%1], 16;" :: "r"(dst), "l"(src) : "memory");
}
#define CP_COMMIT() asm volatile("cp.async.commit_group;" ::: "memory")
#define CP_WAIT1()  asm volatile("cp.async.wait_group 1;" ::: "memory")

__device__ __forceinline__ float tf32r(float x) {
    uint32_t o;
    asm("cvt.rna.tf32.f32 %0, %1;" : "=r"(o) : "f"(x));
    return __uint_as_float(o);
}
#define LDSM4(R, A) \
    asm volatile("ldmatrix.sync.aligned.m8n8.x4.shared.b16 {%0,%1,%2,%3}, [%4];" \
        : "=r"((R)[0]), "=r"((R)[1]), "=r"((R)[2]), "=r"((R)[3]) : "r"(A))

__device__ __forceinline__ void mma_tf32(float* c, const uint32_t* a,
                                         uint32_t b0, uint32_t b1) {
    asm volatile(
        "mma.sync.aligned.m16n8k8.row.col.f32.tf32.tf32.f32 "
        "{%0,%1,%2,%3}, {%4,%5,%6,%7}, {%8,%9}, {%0,%1,%2,%3};"
        : "+f"(c[0]), "+f"(c[1]), "+f"(c[2]), "+f"(c[3])
        : "r"(a[0]), "r"(a[1]), "r"(a[2]), "r"(a[3]), "r"(b0), "r"(b1));
}

// ---------------------------------------------------------------------------
// Kernel 1: S = softmax(relu(E E^T), axis=1), rounded to tf32. One block/row.
// ---------------------------------------------------------------------------
__global__ __launch_bounds__(256) void supports_kernel(const float* __restrict__ emb) {
    __shared__ float logits[NNODES];
    __shared__ float en[EMBD];
    __shared__ float red[256];
    const int n = blockIdx.x;
    const int t = threadIdx.x;
    if (t < EMBD) en[t] = emb[n * EMBD + t];
    __syncthreads();

    float lmax = 0.0f;
    for (int m = t; m < NNODES; m += 256) {
        const float* em = emb + m * EMBD;
        float d = 0.f;
        #pragma unroll
        for (int i = 0; i < EMBD; i++) d += en[i] * em[i];
        d = fmaxf(d, 0.f);
        logits[m] = d;
        lmax = fmaxf(lmax, d);
    }
    red[t] = lmax; __syncthreads();
    for (int s = 128; s > 0; s >>= 1) {
        if (t < s) red[t] = fmaxf(red[t], red[t + s]);
        __syncthreads();
    }
    const float mx = red[0];
    __syncthreads();

    float lsum = 0.f;
    for (int m = t; m < NNODES; m += 256) {
        float e = __expf(logits[m] - mx);
        logits[m] = e;
        lsum += e;
    }
    red[t] = lsum; __syncthreads();
    for (int s = 128; s > 0; s >>= 1) {
        if (t < s) red[t] += red[t + s];
        __syncthreads();
    }
    const float inv = 1.0f / red[0];
    float* Srow = g_S + (size_t)n * NNODES;
    for (int m = t; m < NNODES; m += 256) Srow[m] = tf32r(logits[m] * inv);
}

// ---------------------------------------------------------------------------
// Kernel 2: transpose x[b,m,c] -> Xt[(b*64+c), m], rounded to tf32
// ---------------------------------------------------------------------------
__global__ __launch_bounds__(256) void transpose_kernel(const float* __restrict__ x) {
    __shared__ float Ts[128][68];
    const int t  = threadIdx.x;
    const int m0 = blockIdx.x * 128;
    const int b  = blockIdx.y;

    #pragma unroll
    for (int i = 0; i < 8; i++) {
        const int idx = t + 256 * i;
        const int row = idx >> 4, c4 = idx & 15;
        float4 v = make_float4(0.f, 0.f, 0.f, 0.f);
        if (m0 + row < NNODES)
            v = *(const float4*)&x[((size_t)b * NNODES + m0 + row) * CIN + c4 * 4];
        *(float4*)&Ts[row][c4 * 4] = v;
    }
    __syncthreads();

    #pragma unroll
    for (int i = 0; i < 8; i++) {
        const int o  = t + 256 * i;
        const int c  = o >> 5, mk = o & 31;
        const int m  = m0 + mk * 4;
        if (m + 3 < NNODES) {
            float4 v = make_float4(tf32r(Ts[mk*4+0][c]), tf32r(Ts[mk*4+1][c]),
                                   tf32r(Ts[mk*4+2][c]), tf32r(Ts[mk*4+3][c]));
            *(float4*)&g_Xt[(size_t)(b * 64 + c) * NNODES + m] = v;
        }
    }
}

// ---------------------------------------------------------------------------
// Kernel 3: tf32 mma.sync GEMM  C[128,128] = S_tile[128,4000] @ B_tile^T
//   PHASE 0: B = Xt,  outputs y1n + y1t
//   PHASE 1: B = y1t, outputs y2n
// 8 warps as 2(M) x 4(N); warp tile 64x32; 3-stage cp.async, ldmatrix frags.
// ---------------------------------------------------------------------------
template <int PHASE>
__global__ __launch_bounds__(256, 2) void gemm_mma() {
    extern __shared__ float sm[];
    const uint32_t sBase = smem_u32(sm);

    const float* __restrict__ Bmat = (PHASE == 0) ? g_Xt : g_y1t;
    const int m0 = blockIdx.x * BM;
    const int j0 = blockIdx.y * BN;

    const int t    = threadIdx.x;
    const int lane = t & 31, warp = t >> 5;
    const int wm = warp >> 2, wn = warp & 3;
    const int g = lane >> 2, tig = lane & 3;

    const int lr = t >> 3, lq = t & 7;   // load map: 32 rows x 8 x 16B per pass

    // ldmatrix per-lane base offsets (bytes within a stage)
    //  A x4: m0=(rows+0,cols+0) m1=(rows+8,cols+0) m2=(rows+0,+16B) m3=(rows+8,+16B)
    const uint32_t aOff = (uint32_t)((wm * 64 + (lane & 7) + ((lane >> 3) & 1) * 8) * PADKB
                                     + ((lane >> 4) & 1) * 16);
    //  B x4: m0=(ni0,kLo) m1=(ni0,kHi) m2=(ni1,kLo) m3=(ni1,kHi)
    const uint32_t bOff = (uint32_t)(A_STG
                                     + (wn * 32 + (lane & 7) + ((lane >> 4) & 1) * 8) * PADKB
                                     + ((lane >> 3) & 1) * 16);

    float acc[4][4][4];
    #pragma unroll
    for (int mi = 0; mi < 4; mi++)
        #pragma unroll
        for (int ni = 0; ni < 4; ni++)
            #pragma unroll
            for (int q = 0; q < 4; q++) acc[mi][ni][q] = 0.f;

    auto load_tile = [&](int kt, int s) {
        const size_t kc = (size_t)kt * BK;
        const uint32_t st = sBase + s * STAGE_BYTES;
        #pragma unroll
        for (int i = 0; i < 4; i++) {
            const int r = lr + 32 * i;
            cp16(st + r * PADKB + lq * 16,
                 g_S + (size_t)(m0 + r) * NNODES + kc + lq * 4);
            cp16(st + A_STG + r * PADKB + lq * 16,
                 Bmat + (size_t)(j0 + r) * NNODES + kc + lq * 4);
        }
    };

    load_tile(0, 0); CP_COMMIT();
    load_tile(1, 1); CP_COMMIT();

    int sc = 0;           // compute slot
    int sl = 2;           // load slot (for kt+2)
    for (int kt = 0; kt < KTILES; ++kt) {
        CP_WAIT1();                       // stage kt resident (≤1 group in flight)
        __syncthreads();

        const uint32_t st = sBase + sc * STAGE_BYTES;
        #pragma unroll
        for (int k8 = 0; k8 < 4; ++k8) {
            uint32_t a[4][4], b[2][4];
            #pragma unroll
            for (int mi = 0; mi < 4; mi++)
                LDSM4(a[mi], st + aOff + mi * (16 * PADKB) + k8 * 32);
            LDSM4(b[0], st + bOff + k8 * 32);                   // ni 0,1
            LDSM4(b[1], st + bOff + 16 * PADKB + k8 * 32);      // ni 2,3  (FIXED: +16 rows)
            #pragma unroll
            for (int mi = 0; mi < 4; mi++) {
                mma_tf32(acc[mi][0], a[mi], b[0][0], b[0][1]);
                mma_tf32(acc[mi][1], a[mi], b[0][2], b[0][3]);
                mma_tf32(acc[mi][2], a[mi], b[1][0], b[1][1]);
                mma_tf32(acc[mi][3], a[mi], b[1][2], b[1][3]);
            }
        }

        if (kt + 2 < KTILES) load_tile(kt + 2, sl);
        CP_COMMIT();                      // uniform group count (empty groups OK)
        if (++sc == NSTAGE) sc = 0;
        if (++sl == NSTAGE) sl = 0;
    }

    // ---- epilogue: write y*n normal layout (+ y1t transposed for GEMM2)
    float* __restrict__ outn = (PHASE == 0) ? g_y1n : g_y2n;
    #pragma unroll
    for (int mi = 0; mi < 4; mi++) {
        const int m = m0 + wm * 64 + mi * 16 + g;
        #pragma unroll
        for (int ni = 0; ni < 4; ni++) {
            const float* c = acc[mi][ni];
            const int j = j0 + wn * 32 + ni * 8 + tig * 2;
            const int b = j >> 6, cc = j & 63;
            if (m < NNODES) {
                *(float2*)&outn[((size_t)b * NNODES + m) * CIN + cc] = make_float2(c[0], c[1]);
                if (PHASE == 0) {
                    g_y1t[(size_t)j * NNODES + m]       = tf32r(c[0]);
                    g_y1t[(size_t)(j + 1) * NNODES + m] = tf32r(c[1]);
                }
            }
            const int m2 = m + 8;
            if (m2 < NNODES) {
                *(float2*)&outn[((size_t)b * NNODES + m2) * CIN + cc] = make_float2(c[2], c[3]);
                if (PHASE == 0) {
                    g_y1t[(size_t)j * NNODES + m2]       = tf32r(c[2]);
                    g_y1t[(size_t)(j + 1) * NNODES + m2] = tf32r(c[3]);
                }
            }
        }
    }
}

// ---------------------------------------------------------------------------
// Kernel 4: out[b,n,o] = sum_{k,i} xg_k[b,n,i] * W_k[n,i,o] + bias[n,o]
//   xg_0 = x, xg_1 = y1, xg_2 = 2*y2 - x
// ---------------------------------------------------------------------------
__global__ __launch_bounds__(256) void final_kernel(const float* __restrict__ x,
                                                    const float* __restrict__ emb,
                                                    const float* __restrict__ wp,
                                                    const float* __restrict__ bp,
                                                    float* __restrict__ out) {
    __shared__ __align__(16) float Ws[CIN][COUT];
    __shared__ __align__(16) float Xs[BATCH][68];
    __shared__ float en[EMBD];
    __shared__ float bias_s[COUT];

    const int n = blockIdx.x;
    const int t = threadIdx.x;
    if (t < EMBD) en[t] = emb[n * EMBD + t];
    __syncthreads();
    if (t < COUT) {
        float s = 0.f;
        #pragma unroll
        for (int d = 0; d < EMBD; d++) s += en[d] * bp[d * COUT + t];
        bias_s[t] = s;
    }
    __syncthreads();

    const int ob = (t & 15) * 4;
    const int bb = (t >> 4) * 4;
    float acc[4][4];
    #pragma unroll
    for (int bi = 0; bi < 4; bi++)
        #pragma unroll
        for (int oi = 0; oi < 4; oi++) acc[bi][oi] = bias_s[ob + oi];

    for (int k = 0; k < 3; k++) {
        __syncthreads();

        #pragma unroll
        for (int j = 0; j < 4; j++) {
            const int q  = t + 256 * j;
            const int i  = q >> 4;
            const int o4 = (q & 15) * 4;
            float4 w = make_float4(0.f, 0.f, 0.f, 0.f);
            #pragma unroll
            for (int d = 0; d < EMBD; d++) {
                const float4 wv = *(const float4*)&wp[(((d * 3 + k) * CIN + i) * COUT) + o4];
                const float ed = en[d];
                w.x += ed * wv.x; w.y += ed * wv.y;
                w.z += ed * wv.z; w.w += ed * wv.w;
            }
            *(float4*)&Ws[i][o4] = w;
        }

        #pragma unroll
        for (int j = 0; j < 4; j++) {
            const int q  = t + 256 * j;
            const int b  = q >> 4;
            const int c4 = (q & 15) * 4;
            const size_t off = ((size_t)b * NNODES + n) * CIN + c4;
            float4 v;
            if (k == 0)      v = *(const float4*)&x[off];
            else if (k == 1) v = *(const float4*)&g_y1n[off];
            else {
                const float4 v2 = *(const float4*)&g_y2n[off];
                const float4 vx = *(const float4*)&x[off];
                v = make_float4(2.f * v2.x - vx.x, 2.f * v2.y - vx.y,
                                2.f * v2.z - vx.z, 2.f * v2.w - vx.w);
            }
            *(float4*)&Xs[b][c4] = v;
        }
        __syncthreads();

        #pragma unroll 8
        for (int i = 0; i < CIN; i++) {
            const float4 w = *(const float4*)&Ws[i][ob];
            float xr[4];
            #pragma unroll
            for (int bi = 0; bi < 4; bi++) xr[bi] = Xs[bb + bi][i];
            #pragma unroll
            for (int bi = 0; bi < 4; bi++) {
                acc[bi][0] += xr[bi] * w.x;
                acc[bi][1] += xr[bi] * w.y;
                acc[bi][2] += xr[bi] * w.z;
                acc[bi][3] += xr[bi] * w.w;
            }
        }
    }

    #pragma unroll
    for (int bi = 0; bi < 4; bi++) {
        const size_t off = ((size_t)(bb + bi) * NNODES + n) * COUT + ob;
        *(float4*)&out[off] = make_float4(acc[bi][0], acc[bi][1], acc[bi][2], acc[bi][3]);
    }
}

// ---------------------------------------------------------------------------
extern "C" void kernel_launch(void* const* d_in, const int* in_sizes, int n_in,
                              void* d_out, int out_size) {
    const float* x   = (const float*)d_in[0];   // [B, N, CIN]
    const float* emb = (const float*)d_in[1];   // [N, D]
    const float* wp  = (const float*)d_in[2];   // [D, K, CIN, COUT]
    const float* bp  = (const float*)d_in[3];   // [D, COUT]
    float* out = (float*)d_out;                 // [B, N, COUT]

    cudaFuncSetAttribute(gemm_mma<0>, cudaFuncAttributeMaxDynamicSharedMemorySize, GSMEM);
    cudaFuncSetAttribute(gemm_mma<1>, cudaFuncAttributeMaxDynamicSharedMemorySize, GSMEM);

    supports_kernel<<<NNODES, 256>>>(emb);
    transpose_kernel<<<dim3(32, BATCH), 256>>>(x);

    dim3 g(32, 32);                             // Mtiles x Ntiles
    gemm_mma<0><<<g, 256, GSMEM>>>();           // y1 = S @ x   (-> y1n, y1t)
    gemm_mma<1><<<g, 256, GSMEM>>>();           // y2 = S @ y1  (-> y2n)

    final_kernel<<<NNODES, 256>>>(x, emb, wp, bp, out);
}

// round 11
// speedup vs baseline: 5.4552x; 1.4868x over previous
#include <cuda_runtime.h>
#include <cuda_fp16.h>
#include <cstdint>

#define NNODES 4000
#define NPAD   4096
#define BATCH  64
#define CIN    64
#define COUT   64
#define EMBD   10
#define JDIM   4096            // BATCH * CIN
#define KTILES 125             // 4000 / 32
#define BM     128
#define BN     128
#define BK     32              // halves per k-tile
#define PADHB  80              // smem row stride in BYTES (64B data + 16B pad; 16B-aligned)
#define A_STG  (BM * PADHB)    // 10240 B
#define STAGE_BYTES ((BM + BN) * PADHB)     // 20480 B
#define NSTAGE 4
#define GSMEM  (NSTAGE * STAGE_BYTES)       // 81920 B

// Scratch (allocation-free rule: __device__ globals; zero-initialized at load)
__device__ __half g_Sh [(size_t)NPAD * NNODES];   // rows 4000..4095 stay zero forever
__device__ __half g_Xth[(size_t)JDIM * NNODES];   // x transposed fp16: [(b*64+c), m]
__device__ __half g_y1th[(size_t)JDIM * NNODES];  // y1 transposed fp16 (B of GEMM2)
__device__ float  g_y1n[(size_t)BATCH * NNODES * CIN];
__device__ float  g_y2n[(size_t)BATCH * NNODES * CIN];

// ---------------------------------------------------------------------------
// helpers
// ---------------------------------------------------------------------------
__device__ __forceinline__ uint32_t smem_u32(const void* p) {
    uint32_t a;
    asm("{ .reg .u64 t; cvta.to.shared.u64 t, %1; cvt.u32.u64 %0, t; }" : "=r"(a) : "l"(p));
    return a;
}
__device__ __forceinline__ void cp16(uint32_t dst, const void* src) {
    asm volatile("cp.async.cg.shared.global [%0], [%1], 16;" :: "r"(dst), "l"(src) : "memory");
}
#define CP_COMMIT() asm volatile("cp.async.commit_group;" ::: "memory")
#define CP_WAIT2()  asm volatile("cp.async.wait_group 2;" ::: "memory")

#define LDSM4(R, A) \
    asm volatile("ldmatrix.sync.aligned.m8n8.x4.shared.b16 {%0,%1,%2,%3}, [%4];" \
        : "=r"((R)[0]), "=r"((R)[1]), "=r"((R)[2]), "=r"((R)[3]) : "r"(A))

__device__ __forceinline__ void mma_f16(float* c, const uint32_t* a,
                                        uint32_t b0, uint32_t b1) {
    asm volatile(
        "mma.sync.aligned.m16n8k16.row.col.f32.f16.f16.f32 "
        "{%0,%1,%2,%3}, {%4,%5,%6,%7}, {%8,%9}, {%0,%1,%2,%3};"
        : "+f"(c[0]), "+f"(c[1]), "+f"(c[2]), "+f"(c[3])
        : "r"(a[0]), "r"(a[1]), "r"(a[2]), "r"(a[3]), "r"(b0), "r"(b1));
}

// ---------------------------------------------------------------------------
// Kernel 1: S = softmax(relu(E E^T), axis=1) -> fp16. One block per row.
// ---------------------------------------------------------------------------
__global__ __launch_bounds__(256) void supports_kernel(const float* __restrict__ emb) {
    __shared__ float logits[NNODES];
    __shared__ float en[EMBD];
    __shared__ float red[256];
    const int n = blockIdx.x;
    const int t = threadIdx.x;
    if (t < EMBD) en[t] = emb[n * EMBD + t];
    __syncthreads();

    float lmax = 0.0f;
    for (int m = t; m < NNODES; m += 256) {
        const float* em = emb + m * EMBD;
        float d = 0.f;
        #pragma unroll
        for (int i = 0; i < EMBD; i++) d += en[i] * em[i];
        d = fmaxf(d, 0.f);
        logits[m] = d;
        lmax = fmaxf(lmax, d);
    }
    red[t] = lmax; __syncthreads();
    for (int s = 128; s > 0; s >>= 1) {
        if (t < s) red[t] = fmaxf(red[t], red[t + s]);
        __syncthreads();
    }
    const float mx = red[0];
    __syncthreads();

    float lsum = 0.f;
    for (int m = t; m < NNODES; m += 256) {
        float e = __expf(logits[m] - mx);
        logits[m] = e;
        lsum += e;
    }
    red[t] = lsum; __syncthreads();
    for (int s = 128; s > 0; s >>= 1) {
        if (t < s) red[t] += red[t + s];
        __syncthreads();
    }
    const float inv = 1.0f / red[0];
    __half* Srow = g_Sh + (size_t)n * NNODES;
    for (int m = t; m < NNODES; m += 256) Srow[m] = __float2half_rn(logits[m] * inv);
}

// ---------------------------------------------------------------------------
// Kernel 2: transpose x[b,m,c] -> Xth[(b*64+c), m] fp16
// ---------------------------------------------------------------------------
__global__ __launch_bounds__(256) void transpose_kernel(const float* __restrict__ x) {
    __shared__ float Ts[128][68];
    const int t  = threadIdx.x;
    const int m0 = blockIdx.x * 128;
    const int b  = blockIdx.y;

    #pragma unroll
    for (int i = 0; i < 8; i++) {
        const int idx = t + 256 * i;
        const int row = idx >> 4, c4 = idx & 15;
        float4 v = make_float4(0.f, 0.f, 0.f, 0.f);
        if (m0 + row < NNODES)
            v = *(const float4*)&x[((size_t)b * NNODES + m0 + row) * CIN + c4 * 4];
        *(float4*)&Ts[row][c4 * 4] = v;
    }
    __syncthreads();

    #pragma unroll
    for (int i = 0; i < 8; i++) {
        const int o  = t + 256 * i;
        const int c  = o >> 5, mk = o & 31;
        const int m  = m0 + mk * 4;
        if (m + 3 < NNODES) {
            __half2 p0 = __floats2half2_rn(Ts[mk*4+0][c], Ts[mk*4+1][c]);
            __half2 p1 = __floats2half2_rn(Ts[mk*4+2][c], Ts[mk*4+3][c]);
            __half* dst = &g_Xth[(size_t)(b * 64 + c) * NNODES + m];
            *(__half2*)(dst)     = p0;
            *(__half2*)(dst + 2) = p1;
        }
    }
}

// ---------------------------------------------------------------------------
// Kernel 3: fp16 mma.sync GEMM  C[128,128] = S_tile[128,4000] @ B_tile^T
//   PHASE 0: B = Xth,  outputs y1n + y1th
//   PHASE 1: B = y1th, outputs y2n
// 8 warps as 2(M) x 4(N); warp tile 64x32; 4-stage cp.async, ldmatrix frags.
// ---------------------------------------------------------------------------
template <int PHASE>
__global__ __launch_bounds__(256, 2) void gemm_mma() {
    extern __shared__ char sm[];
    const uint32_t sBase = smem_u32(sm);

    const __half* __restrict__ Bmat = (PHASE == 0) ? g_Xth : g_y1th;
    const int m0 = blockIdx.x * BM;
    const int j0 = blockIdx.y * BN;

    const int t    = threadIdx.x;
    const int lane = t & 31, warp = t >> 5;
    const int wm = warp >> 2, wn = warp & 3;
    const int g = lane >> 2, tig = lane & 3;

    const int lr = t >> 2, lq = t & 3;   // load map: 64 rows x 4 x 16B per pass

    // ldmatrix per-lane base offsets (bytes within a stage)
    //  A x4: r0=(rows+0,kLo) r1=(rows+8,kLo) r2=(rows+0,kHi) r3=(rows+8,kHi)
    const uint32_t aOff = (uint32_t)((wm * 64 + (lane & 7) + ((lane >> 3) & 1) * 8) * PADHB
                                     + ((lane >> 4) & 1) * 16);
    //  B x4: r0=(n0-7,kLo) r1=(n0-7,kHi) r2=(n8-15,kLo) r3=(n8-15,kHi)
    const uint32_t bOff = (uint32_t)(A_STG
                                     + (wn * 32 + (lane & 7) + ((lane >> 4) & 1) * 8) * PADHB
                                     + ((lane >> 3) & 1) * 16);

    float acc[4][4][4];
    #pragma unroll
    for (int mi = 0; mi < 4; mi++)
        #pragma unroll
        for (int ni = 0; ni < 4; ni++)
            #pragma unroll
            for (int q = 0; q < 4; q++) acc[mi][ni][q] = 0.f;

    auto load_tile = [&](int kt, int s) {
        const size_t kc = (size_t)kt * BK;           // in halves
        const uint32_t st = sBase + s * STAGE_BYTES;
        #pragma unroll
        for (int i = 0; i < 2; i++) {
            const int r = lr + 64 * i;               // 0..127
            cp16(st + r * PADHB + lq * 16,
                 g_Sh + (size_t)(m0 + r) * NNODES + kc + lq * 8);
            cp16(st + A_STG + r * PADHB + lq * 16,
                 Bmat + (size_t)(j0 + r) * NNODES + kc + lq * 8);
        }
    };

    load_tile(0, 0); CP_COMMIT();
    load_tile(1, 1); CP_COMMIT();
    load_tile(2, 2); CP_COMMIT();

    int sc = 0;           // compute slot
    int sl = 3;           // load slot (for kt+3)
    for (int kt = 0; kt < KTILES; ++kt) {
        CP_WAIT2();                       // stage kt resident (≤2 groups in flight)
        __syncthreads();

        const uint32_t st = sBase + sc * STAGE_BYTES;
        #pragma unroll
        for (int k16 = 0; k16 < 2; ++k16) {
            uint32_t a[4][4], b[2][4];
            #pragma unroll
            for (int mi = 0; mi < 4; mi++)
                LDSM4(a[mi], st + aOff + mi * (16 * PADHB) + k16 * 32);
            LDSM4(b[0], st + bOff + k16 * 32);                   // n 0..15
            LDSM4(b[1], st + bOff + 16 * PADHB + k16 * 32);      // n 16..31
            #pragma unroll
            for (int mi = 0; mi < 4; mi++) {
                mma_f16(acc[mi][0], a[mi], b[0][0], b[0][1]);
                mma_f16(acc[mi][1], a[mi], b[0][2], b[0][3]);
                mma_f16(acc[mi][2], a[mi], b[1][0], b[1][1]);
                mma_f16(acc[mi][3], a[mi], b[1][2], b[1][3]);
            }
        }

        if (kt + 3 < KTILES) load_tile(kt + 3, sl);
        CP_COMMIT();                      // uniform group count (empty groups OK)
        if (++sc == NSTAGE) sc = 0;
        if (++sl == NSTAGE) sl = 0;
    }

    // ---- epilogue: write y*n normal layout (+ y1th transposed for GEMM2)
    float* __restrict__ outn = (PHASE == 0) ? g_y1n : g_y2n;
    #pragma unroll
    for (int mi = 0; mi < 4; mi++) {
        const int m = m0 + wm * 64 + mi * 16 + g;
        #pragma unroll
        for (int ni = 0; ni < 4; ni++) {
            const float* c = acc[mi][ni];
            const int j = j0 + wn * 32 + ni * 8 + tig * 2;
            const int b = j >> 6, cc = j & 63;
            if (m < NNODES) {
                *(float2*)&outn[((size_t)b * NNODES + m) * CIN + cc] = make_float2(c[0], c[1]);
                if (PHASE == 0) {
                    g_y1th[(size_t)j * NNODES + m]       = __float2half_rn(c[0]);
                    g_y1th[(size_t)(j + 1) * NNODES + m] = __float2half_rn(c[1]);
                }
            }
            const int m2 = m + 8;
            if (m2 < NNODES) {
                *(float2*)&outn[((size_t)b * NNODES + m2) * CIN + cc] = make_float2(c[2], c[3]);
                if (PHASE == 0) {
                    g_y1th[(size_t)j * NNODES + m2]       = __float2half_rn(c[2]);
                    g_y1th[(size_t)(j + 1) * NNODES + m2] = __float2half_rn(c[3]);
                }
            }
        }
    }
}

// ---------------------------------------------------------------------------
// Kernel 4: out[b,n,o] = sum_{k,i} xg_k[b,n,i] * W_k[n,i,o] + bias[n,o]
//   xg_0 = x, xg_1 = y1, xg_2 = 2*y2 - x
// ---------------------------------------------------------------------------
__global__ __launch_bounds__(256) void final_kernel(const float* __restrict__ x,
                                                    const float* __restrict__ emb,
                                                    const float* __restrict__ wp,
                                                    const float* __restrict__ bp,
                                                    float* __restrict__ out) {
    __shared__ __align__(16) float Ws[CIN][COUT];
    __shared__ __align__(16) float Xs[BATCH][68];
    __shared__ float en[EMBD];
    __shared__ float bias_s[COUT];

    const int n = blockIdx.x;
    const int t = threadIdx.x;
    if (t < EMBD) en[t] = emb[n * EMBD + t];
    __syncthreads();
    if (t < COUT) {
        float s = 0.f;
        #pragma unroll
        for (int d = 0; d < EMBD; d++) s += en[d] * bp[d * COUT + t];
        bias_s[t] = s;
    }
    __syncthreads();

    const int ob = (t & 15) * 4;
    const int bb = (t >> 4) * 4;
    float acc[4][4];
    #pragma unroll
    for (int bi = 0; bi < 4; bi++)
        #pragma unroll
        for (int oi = 0; oi < 4; oi++) acc[bi][oi] = bias_s[ob + oi];

    for (int k = 0; k < 3; k++) {
        __syncthreads();

        #pragma unroll
        for (int j = 0; j < 4; j++) {
            const int q  = t + 256 * j;
            const int i  = q >> 4;
            const int o4 = (q & 15) * 4;
            float4 w = make_float4(0.f, 0.f, 0.f, 0.f);
            #pragma unroll
            for (int d = 0; d < EMBD; d++) {
                const float4 wv = *(const float4*)&wp[(((d * 3 + k) * CIN + i) * COUT) + o4];
                const float ed = en[d];
                w.x += ed * wv.x; w.y += ed * wv.y;
                w.z += ed * wv.z; w.w += ed * wv.w;
            }
            *(float4*)&Ws[i][o4] = w;
        }

        #pragma unroll
        for (int j = 0; j < 4; j++) {
            const int q  = t + 256 * j;
            const int b  = q >> 4;
            const int c4 = (q & 15) * 4;
            const size_t off = ((size_t)b * NNODES + n) * CIN + c4;
            float4 v;
            if (k == 0)      v = *(const float4*)&x[off];
            else if (k == 1) v = *(const float4*)&g_y1n[off];
            else {
                const float4 v2 = *(const float4*)&g_y2n[off];
                const float4 vx = *(const float4*)&x[off];
                v = make_float4(2.f * v2.x - vx.x, 2.f * v2.y - vx.y,
                                2.f * v2.z - vx.z, 2.f * v2.w - vx.w);
            }
            *(float4*)&Xs[b][c4] = v;
        }
        __syncthreads();

        #pragma unroll 8
        for (int i = 0; i < CIN; i++) {
            const float4 w = *(const float4*)&Ws[i][ob];
            float xr[4];
            #pragma unroll
            for (int bi = 0; bi < 4; bi++) xr[bi] = Xs[bb + bi][i];
            #pragma unroll
            for (int bi = 0; bi < 4; bi++) {
                acc[bi][0] += xr[bi] * w.x;
                acc[bi][1] += xr[bi] * w.y;
                acc[bi][2] += xr[bi] * w.z;
                acc[bi][3] += xr[bi] * w.w;
            }
        }
    }

    #pragma unroll
    for (int bi = 0; bi < 4; bi++) {
        const size_t off = ((size_t)(bb + bi) * NNODES + n) * COUT + ob;
        *(float4*)&out[off] = make_float4(acc[bi][0], acc[bi][1], acc[bi][2], acc[bi][3]);
    }
}

// ---------------------------------------------------------------------------
extern "C" void kernel_launch(void* const* d_in, const int* in_sizes, int n_in,
                              void* d_out, int out_size) {
    const float* x   = (const float*)d_in[0];   // [B, N, CIN]
    const float* emb = (const float*)d_in[1];   // [N, D]
    const float* wp  = (const float*)d_in[2];   // [D, K, CIN, COUT]
    const float* bp  = (const float*)d_in[3];   // [D, COUT]
    float* out = (float*)d_out;                 // [B, N, COUT]

    cudaFuncSetAttribute(gemm_mma<0>, cudaFuncAttributeMaxDynamicSharedMemorySize, GSMEM);
    cudaFuncSetAttribute(gemm_mma<1>, cudaFuncAttributeMaxDynamicSharedMemorySize, GSMEM);

    supports_kernel<<<NNODES, 256>>>(emb);
    transpose_kernel<<<dim3(32, BATCH), 256>>>(x);

    dim3 g(32, 32);                             // Mtiles x Ntiles
    gemm_mma<0><<<g, 256, GSMEM>>>();           // y1 = S @ x   (-> y1n, y1th)
    gemm_mma<1><<<g, 256, GSMEM>>>();           // y2 = S @ y1  (-> y2n)

    final_kernel<<<NNODES, 256>>>(x, emb, wp, bp, out);
}